// round 17
// baseline (speedup 1.0000x reference)
#include <cuda_runtime.h>
#include <cuda_fp16.h>
#include <stdint.h>
#include <math.h>

// ---------------------------------------------------------------------------
// SimpleMamba via warp-level mma.sync fp16 GEMM (single product).
//   R17 = R16 (531.3us) + parallel combine (32 blocks, deterministic
//   last-block finalize) + 8-way split scan (serial chain halved again).
//   Mainloop/gates/prep untouched (R10 plateau, prep at DRAM cap).
// ---------------------------------------------------------------------------

#define DM    1024
#define KD    1024
#define BM    128
#define BNC   64
#define BK    64
#define KTPT  16
#define NCHUNK 32
#define ASTR  66
#define NTILE 4096
#define NCTA  148

#define STAGE_BYTES 40960    // Ah 16K + Bh 24K
#define OFF_BH  16384
#define SCAN_OFF (3 * STAGE_BYTES)
#define SMEM_TOTAL (SCAN_OFF + 2 * BM * ASTR * 4)  // 190464

#define NTH 512

// ---------------- device scratch ----------------
__device__ __align__(128) __half g_Ah[32768u * 1024u];
__device__ __align__(128) __half g_Bh[3u * 1024u * 1024u];   // interleaved rows
__device__ float g_P[8 * NCHUNK * DM];
__device__ float g_S[8 * NCHUNK * DM];
__device__ float g_part[32 * 3];          // per-combine-block partials
__device__ unsigned int g_cdone = 0;

// ---------------- helpers ----------------
static __device__ __forceinline__ uint32_t smem_u32(const void* p) {
    uint32_t a;
    asm("{ .reg .u64 t; cvta.to.shared.u64 t, %1; cvt.u32.u64 %0, t; }" : "=r"(a) : "l"(p));
    return a;
}
static __device__ __forceinline__ uint32_t sw128(uint32_t o) { return o ^ ((o >> 3) & 0x70); }

static __device__ __forceinline__ void cp16(uint32_t dst, const void* src) {
    asm volatile("cp.async.cg.shared.global [%0], [%1], 16;" :: "r"(dst), "l"(src) : "memory");
}
static __device__ __forceinline__ void ldsm4(uint32_t* r, uint32_t addr) {
    asm volatile("ldmatrix.sync.aligned.m8n8.x4.shared.b16 {%0,%1,%2,%3}, [%4];"
        : "=r"(r[0]), "=r"(r[1]), "=r"(r[2]), "=r"(r[3]) : "r"(addr));
}
static __device__ __forceinline__ void mma_f16(float* c, const uint32_t* a,
                                               uint32_t b0, uint32_t b1) {
    asm volatile("mma.sync.aligned.m16n8k16.row.col.f32.f16.f16.f32 "
        "{%0,%1,%2,%3}, {%4,%5,%6,%7}, {%8,%9}, {%0,%1,%2,%3};"
        : "+f"(c[0]), "+f"(c[1]), "+f"(c[2]), "+f"(c[3])
        : "r"(a[0]), "r"(a[1]), "r"(a[2]), "r"(a[3]), "r"(b0), "r"(b1));
}

static __device__ __forceinline__ float softplus_f(float z) {
    return fmaxf(z, 0.0f) + __logf(1.0f + __expf(-fabsf(z)));
}

// ---------------- merged prep kernel (vectorized) ----------------
__global__ void __launch_bounds__(256)
prep_kernel(const float* __restrict__ x, const float* __restrict__ Wl,
            const float* __restrict__ Wd, const float* __restrict__ Wb) {
    const int tid = threadIdx.x;
    if (blockIdx.x < 16384) {
        size_t i = (size_t)blockIdx.x * 256 + tid;   // 8-float group index
        float4 v0 = ((const float4*)x)[2 * i];
        float4 v1 = ((const float4*)x)[2 * i + 1];
        __half2 h[4];
        h[0] = __floats2half2_rn(v0.x, v0.y);
        h[1] = __floats2half2_rn(v0.z, v0.w);
        h[2] = __floats2half2_rn(v1.x, v1.y);
        h[3] = __floats2half2_rn(v1.z, v1.w);
        ((uint4*)g_Ah)[i] = *(const uint4*)h;
    } else {
        const int bid = blockIdx.x - 16384;        // 0..3071
        const int mat = bid >> 10;
        const int rem = bid & 1023;
        const int k0 = (rem >> 5) * 32;
        const int n0 = (rem & 31) * 32;
        const float* W = (mat == 0) ? Wl : (mat == 1) ? Wd : Wb;
        __shared__ float ts[32][33];
        const int tx = tid & 31, ty = tid >> 5;
#pragma unroll
        for (int i = 0; i < 4; i++) {
            int k = ty + i * 8;
            ts[k][tx] = W[(size_t)(k0 + k) * DM + n0 + tx];
        }
        __syncthreads();
#pragma unroll
        for (int i = 0; i < 4; i++) {
            int n = n0 + ty + i * 8;
            int row = (n >> 4) * 48 + mat * 16 + (n & 15);
            g_Bh[(size_t)row * KD + k0 + tx] = __float2half(ts[tx][ty + i * 8]);
        }
    }
}

// ---------------- GEMM + scan (persistent, R10 mainloop verbatim) ----------------
static __device__ __forceinline__ void load_stage(int s, int cta, int tid, uint32_t sb) {
    const int tile = cta + NCTA * (s >> 4);
    const int kt = s & 15;
    const int R = (tile >> 4) * BM;
    const int Crow = (tile & 15) * 192;
    const uint32_t st = sb + (s % 3) * STAGE_BYTES;
#pragma unroll
    for (int i = 0; i < 2; i++) {
        int c = i * NTH + tid;
        int row = c >> 3, q = c & 7;
        size_t g = ((size_t)(R + row) << 10) + kt * BK + q * 8;
        cp16(st + sw128((uint32_t)(row * 128 + q * 16)), g_Ah + g);
    }
#pragma unroll
    for (int i = 0; i < 3; i++) {
        int c = i * NTH + tid;
        int row = c >> 3, q = c & 7;
        size_t g = ((size_t)(Crow + row) << 10) + kt * BK + q * 8;
        cp16(st + OFF_BH + sw128((uint32_t)(row * 128 + q * 16)), g_Bh + g);
    }
    asm volatile("cp.async.commit_group;" ::: "memory");
}

static __device__ __forceinline__ void frag_load(uint32_t A[2][4], uint32_t B[3][4],
                                                 uint32_t st, int kb,
                                                 int a_row_l, int a_cb,
                                                 int b_row_l, int b_cb) {
#pragma unroll
    for (int mt = 0; mt < 2; mt++)
        ldsm4(A[mt], st + sw128((uint32_t)((a_row_l + mt * 16) * 128 + kb + a_cb)));
#pragma unroll
    for (int nt = 0; nt < 3; nt++)
        ldsm4(B[nt], st + OFF_BH + sw128((uint32_t)((b_row_l + nt * 16) * 128 + kb + b_cb)));
}

static __device__ __forceinline__ void do_mma(float acc[2][6][4],
                                              uint32_t A[2][4], uint32_t B[3][4]) {
#pragma unroll
    for (int mt = 0; mt < 2; mt++)
#pragma unroll
        for (int nt = 0; nt < 3; nt++) {
            mma_f16(acc[mt][2 * nt],     A[mt], B[nt][0], B[nt][1]);
            mma_f16(acc[mt][2 * nt + 1], A[mt], B[nt][2], B[nt][3]);
        }
}

__global__ void __launch_bounds__(NTH)
mamba_gemm_mma(const float* __restrict__ pbl, const float* __restrict__ pbd,
               const float* __restrict__ pbb) {
    extern __shared__ char smem[];
    const uint32_t sb = smem_u32(smem);
    const int tid = threadIdx.x;
    const int warp = tid >> 5;
    const int lane = tid & 31;
    const int cta = blockIdx.x;
    const int wm = warp >> 2;
    const int wn = warp & 3;

    const int ntiles = (NTILE - cta + NCTA - 1) / NCTA;
    const int G = ntiles * KTPT;

    float* SA = (float*)(smem + SCAN_OFF);
    float* SD = SA + BM * ASTR;
    __shared__ float sP[8][BNC], sS[8][BNC];

    float acc[2][6][4];
#pragma unroll
    for (int i = 0; i < 2; i++)
#pragma unroll
        for (int j = 0; j < 6; j++)
#pragma unroll
            for (int k = 0; k < 4; k++) acc[i][j][k] = 0.0f;

    const int a_row_l = wm * 32 + (lane & 15);
    const int a_cb = (lane >> 4) * 16;
    const int b_row_l = wn * 48 + ((lane >> 4) & 1) * 8 + (lane & 7);
    const int b_cb = ((lane >> 3) & 1) * 16;
    const int q2 = 2 * (lane & 3);

    uint32_t Af[2][2][4], Bf[2][3][4];

    load_stage(0, cta, tid, sb);
    load_stage(1, cta, tid, sb);
    asm volatile("cp.async.wait_group 1;" ::: "memory");
    __syncthreads();
    frag_load(Af[0], Bf[0], sb, 0, a_row_l, a_cb, b_row_l, b_cb);

    for (int s = 0; s < G; s++) {
        const uint32_t st = sb + (s % 3) * STAGE_BYTES;
        if (s + 2 < G) load_stage(s + 2, cta, tid, sb);
#pragma unroll
        for (int ks = 0; ks < 4; ks++) {
            const int cur = ks & 1, nxt = cur ^ 1;
            if (ks < 3) {
                frag_load(Af[nxt], Bf[nxt], st, (ks + 1) * 32,
                          a_row_l, a_cb, b_row_l, b_cb);
            } else if (s + 1 < G) {
                if (s + 2 < G)
                    asm volatile("cp.async.wait_group 1;" ::: "memory");
                else
                    asm volatile("cp.async.wait_group 0;" ::: "memory");
                __syncthreads();
                frag_load(Af[nxt], Bf[nxt], sb + ((s + 1) % 3) * STAGE_BYTES, 0,
                          a_row_l, a_cb, b_row_l, b_cb);
            }
            do_mma(acc, Af[cur], Bf[cur]);
        }

        if ((s & (KTPT - 1)) == KTPT - 1) {
            const int tile = cta + NCTA * (s >> 4);
            const int R = (tile >> 4) * BM;
            const int C = (tile & 15) * BNC;

            {
                float bl_[2][2], bd_[2][2], bb_[2][2];
#pragma unroll
                for (int g = 0; g < 2; g++)
#pragma unroll
                    for (int e = 0; e < 2; e++) {
                        const int gc = C + wn * 16 + g * 8 + q2 + e;
                        bl_[g][e] = __ldg(pbl + gc);
                        bd_[g][e] = __ldg(pbd + gc);
                        bb_[g][e] = __ldg(pbb + gc);
                    }
#pragma unroll
                for (int mt = 0; mt < 2; mt++)
#pragma unroll
                    for (int h = 0; h < 2; h++) {
                        const int row = wm * 32 + mt * 16 + (lane >> 2) + 8 * h;
#pragma unroll
                        for (int g = 0; g < 2; g++) {
                            float a0, a1, d0, d1;
#pragma unroll
                            for (int e = 0; e < 2; e++) {
                                float lam = softplus_f(acc[mt][g][2 * h + e]     + bl_[g][e]);
                                float de  = softplus_f(acc[mt][2 + g][2 * h + e] + bd_[g][e]);
                                float u   = acc[mt][4 + g][2 * h + e] + bb_[g][e];
                                float al  = __expf(-de * lam);
                                float dr  = de * u;
                                if (e == 0) { a0 = al; d0 = dr; } else { a1 = al; d1 = dr; }
                            }
                            const int ch = wn * 16 + g * 8 + q2;
                            *(float2*)&SA[row * ASTR + ch] = make_float2(a0, a1);
                            *(float2*)&SD[row * ASTR + ch] = make_float2(d0, d1);
                        }
                    }
            }
            __syncthreads();

            // ---- 8-way split scan: 512 threads, 16 rows each ----
            {
                const int ch = tid & 63;
                const int oc = tid >> 6;       // 0..7
                float sc = 0.0f, P = 1.0f;
                const int t0 = oc * 16;
#pragma unroll 8
                for (int t = t0; t < t0 + 16; t++) {
                    float a = SA[t * ASTR + ch];
                    float d = SD[t * ASTR + ch];
                    sc = fmaf(a, sc, d);
                    P *= a;
                }
                sP[oc][ch] = P;
                sS[oc][ch] = sc;
            }
            __syncthreads();
            if (tid < BNC) {
                float P = sP[0][tid];
                float sc = sS[0][tid];
#pragma unroll
                for (int oc = 1; oc < 8; oc++) {
                    sc = fmaf(sP[oc][tid], sc, sS[oc][tid]);
                    P *= sP[oc][tid];
                }
                const int bidx = R >> 12;
                const int chunk = (R >> 7) & 31;
                const int idx = ((bidx * NCHUNK + chunk) << 10) + C + tid;
                g_P[idx] = P;
                g_S[idx] = sc;
            }

            // no trailing __syncthreads: next SA/SD write is 16 stages away,
            // with a barrier at every stage boundary in between.
#pragma unroll
            for (int i = 0; i < 2; i++)
#pragma unroll
                for (int j = 0; j < 6; j++)
#pragma unroll
                    for (int k = 0; k < 4; k++) acc[i][j][k] = 0.0f;
        }
    }
}

// ---------------- parallel combine: 32 blocks + last-block finalize ----------------
// block = b*4 + part;  channels [part*256, part*256+256)
__global__ void __launch_bounds__(1024)
combine_kernel(const float* __restrict__ W_par, const float* __restrict__ b_par,
               const float* __restrict__ W_add, const float* __restrict__ b_add,
               float* __restrict__ out)
{
    const int blk = blockIdx.x;
    const int b = blk >> 2;
    const int part = blk & 3;
    const int tid = threadIdx.x;
    const int lane = tid & 31, warp = tid >> 5;

    const int ch = tid & 255;          // channel within part
    const int seg = tid >> 8;          // 0..3, 8 chunks each
    const int d = part * 256 + ch;

    // segment (P,S) over chunks [seg*8, seg*8+8)
    float s = 0.0f, P = 1.0f;
#pragma unroll
    for (int k = 0; k < 8; k++) {
        const int c = seg * 8 + k;
        const int idx = ((b * NCHUNK + c) << 10) + d;
        s = fmaf(g_P[idx], s, g_S[idx]);
        P *= g_P[idx];
    }
    __shared__ float segP[4][256], segS[4][256];
    segP[seg][ch] = P;
    segS[seg][ch] = s;
    __syncthreads();

    float v0 = 0.0f, v1 = 0.0f, v2 = 0.0f;
    if (tid < 256) {
        float sc = segS[0][tid];
#pragma unroll
        for (int sg = 1; sg < 4; sg++)
            sc = fmaf(segP[sg][tid], sc, segS[sg][tid]);
        const int dd = part * 256 + tid;
        v0 = sc * W_par[2 * dd];
        v1 = sc * W_par[2 * dd + 1];
        v2 = sc * W_add[dd];
    }
    // warps 0-7 fully cover tid<256 -> uniform shuffles
    if (warp < 8) {
#pragma unroll
        for (int o = 16; o > 0; o >>= 1) {
            v0 += __shfl_xor_sync(0xffffffffu, v0, o);
            v1 += __shfl_xor_sync(0xffffffffu, v1, o);
            v2 += __shfl_xor_sync(0xffffffffu, v2, o);
        }
    }
    __shared__ float r0[8], r1[8], r2[8];
    if (warp < 8 && lane == 0) { r0[warp] = v0; r1[warp] = v1; r2[warp] = v2; }
    __syncthreads();
    if (tid == 0) {
        float t0 = 0.0f, t1 = 0.0f, t2 = 0.0f;
#pragma unroll
        for (int w = 0; w < 8; w++) { t0 += r0[w]; t1 += r1[w]; t2 += r2[w]; }
        g_part[blk * 3 + 0] = t0;
        g_part[blk * 3 + 1] = t1;
        g_part[blk * 3 + 2] = t2;
    }
    __syncthreads();

    // last block finalizes (deterministic fixed-order partial sum)
    __threadfence();
    __shared__ unsigned int last;
    if (tid == 0) last = atomicAdd(&g_cdone, 1u);
    __syncthreads();
    if (last == 31) {
        __threadfence();
        if (tid < 8) {
            const int bb = tid;
            float t0 = 0.0f, t1 = 0.0f, t2 = 0.0f;
#pragma unroll
            for (int p = 0; p < 4; p++) {
                t0 += g_part[(bb * 4 + p) * 3 + 0];
                t1 += g_part[(bb * 4 + p) * 3 + 1];
                t2 += g_part[(bb * 4 + p) * 3 + 2];
            }
            out[2 * bb]     = t0 + b_par[0];
            out[2 * bb + 1] = t1 + b_par[1];
            out[16 + bb]    = t2 + b_add[0];
        }
        if (tid == 0) g_cdone = 0;   // reset for graph replay
    }
}

extern "C" void kernel_launch(void* const* d_in, const int* in_sizes, int n_in,
                              void* d_out, int out_size)
{
    const float* x  = (const float*)d_in[0];
    const float* Wl = (const float*)d_in[1];
    const float* bl = (const float*)d_in[2];
    const float* Wd = (const float*)d_in[3];
    const float* bd = (const float*)d_in[4];
    const float* Wb = (const float*)d_in[5];
    const float* bb = (const float*)d_in[6];
    const float* Wp = (const float*)d_in[7];
    const float* bp = (const float*)d_in[8];
    const float* Wa = (const float*)d_in[9];
    const float* ba = (const float*)d_in[10];
    float* out = (float*)d_out;

    cudaFuncSetAttribute(mamba_gemm_mma,
                         cudaFuncAttributeMaxDynamicSharedMemorySize, SMEM_TOTAL);

    prep_kernel<<<16384 + 3072, 256>>>(x, Wl, Wd, Wb);
    mamba_gemm_mma<<<NCTA, NTH, SMEM_TOTAL>>>(bl, bd, bb);
    combine_kernel<<<32, 1024>>>(Wp, bp, Wa, ba, out);
}